// round 3
// baseline (speedup 1.0000x reference)
#include <cuda_runtime.h>
#include <math.h>

#define HH 512
#define WW 512
#define NACC 72          // 45 AtA upper-tri + 27 Atb
#define NXB 2
#define NSTR 37
#define NPART (NXB * NSTR)   // 74 blocks per batch image
#define BMAX 8

__device__ float g_part[BMAX * NPART * NACC];

typedef unsigned long long u64;

__device__ __forceinline__ u64 pk2(float lo, float hi) {
    u64 r; asm("mov.b64 %0,{%1,%2};" : "=l"(r) : "f"(lo), "f"(hi)); return r;
}
__device__ __forceinline__ void upk2(u64 a, float& lo, float& hi) {
    asm("mov.b64 {%0,%1},%2;" : "=f"(lo), "=f"(hi) : "l"(a));
}
__device__ __forceinline__ u64 fma2(u64 a, u64 b, u64 c) {
    u64 d; asm("fma.rn.f32x2 %0,%1,%2,%3;" : "=l"(d) : "l"(a), "l"(b), "l"(c)); return d;
}
__device__ __forceinline__ u64 mul2(u64 a, u64 b) {
    u64 d; asm("mul.rn.f32x2 %0,%1,%2;" : "=l"(d) : "l"(a), "l"(b)); return d;
}
__device__ __forceinline__ u64 add2(u64 a, u64 b) {
    u64 d; asm("add.rn.f32x2 %0,%1,%2;" : "=l"(d) : "l"(a), "l"(b)); return d;
}
__device__ __forceinline__ u64 neg2(u64 a) { return a ^ 0x8000000080000000ULL; }
// a - b  (exact: fma(b, -1, a) rounds the exact difference once)
__device__ __forceinline__ u64 sub2(u64 a, u64 b) { return fma2(b, 0xBF800000BF800000ULL, a); }
// a*b - c
__device__ __forceinline__ u64 fms2(u64 a, u64 b, u64 c) { return fma2(a, b, neg2(c)); }
__device__ __forceinline__ u64 bcast2(float v) { return pk2(v, v); }

__global__ __launch_bounds__(128) void accum_k(const float* __restrict__ img,
                                               const float* __restrict__ dep,
                                               const float* __restrict__ alb) {
    const int tid = threadIdx.x;
    const int xb = blockIdx.x;   // 0..1
    const int st = blockIdx.y;   // 0..36
    const int b  = blockIdx.z;

    const int x_lo = 1 + xb * 256 + tid;    // <= 384, always valid
    int x_hi = x_lo + 128;
    const bool v_hi = (x_hi <= 510);
    if (!v_hi) x_hi = 510;                  // clamp; contribution zeroed below

    const int y0 = 1 + (510 * st) / NSTR;
    const int y1 = 1 + (510 * (st + 1)) / NSTR;

    const float* __restrict__ D  = dep + (size_t)b * HH * WW;
    const float* __restrict__ I0 = img + (size_t)b * 3 * HH * WW;
    const float* __restrict__ I1 = I0 + HH * WW;
    const float* __restrict__ I2 = I1 + HH * WW;
    const float* __restrict__ A2 = alb + (size_t)b * 3 * HH * WW + 2 * HH * WW;

    const float INVF = (float)(1.0 / 608.365);
    const double PI_ = 3.14159;
    const float C0 = (float)(PI_ * sqrt(1.0 / (4.0 * PI_)));
    const float C1 = (float)(2.0 * PI_ / 3.0 * sqrt(3.0 / (4.0 * PI_)));
    const float C2 = (float)(PI_ / 4.0 * 0.5 * sqrt(5.0 / (4.0 * PI_)));
    const float C3 = (float)(PI_ / 4.0 * 3.0 * sqrt(5.0 / (12.0 * PI_)));
    const float C4 = (float)(PI_ / 4.0 * 3.0 * sqrt(5.0 / (48.0 * PI_)));
    const u64 C0_2 = bcast2(C0), C1_2 = bcast2(C1), C2_2 = bcast2(C2);
    const u64 C3_2 = bcast2(C3), C4_2 = bcast2(C4);
    const u64 HALF2  = 0x3F0000003F000000ULL;
    const u64 THREE2 = 0x4040000040400000ULL;

    // per-thread-constant x coordinates (packed)
    const u64 u2  = pk2((x_lo     - 256.0f) * INVF, (x_hi     - 256.0f) * INVF);
    const u64 uE2 = pk2((x_lo + 1 - 256.0f) * INVF, (x_hi + 1 - 256.0f) * INVF);
    const u64 uW2 = pk2((x_lo - 1 - 256.0f) * INVF, (x_hi - 1 - 256.0f) * INVF);

    u64 s2[NACC];
#pragma unroll
    for (int k = 0; k < NACC; k++) s2[k] = 0ULL;

    // preload center-column depth, rows y0-1 and y0 (transform d -> (d+1)/2)
    u64 dN2 = fma2(pk2(D[(y0 - 1) * WW + x_lo], D[(y0 - 1) * WW + x_hi]), HALF2, HALF2);
    u64 dC2 = fma2(pk2(D[y0 * WW + x_lo],       D[y0 * WW + x_hi]),       HALF2, HALF2);

    for (int y = y0; y < y1; y++) {
        const int row = y * WW;
        // fresh loads: south center, east, west (3 depth loads/pixel)
        u64 dS2 = fma2(pk2(D[row + WW + x_lo], D[row + WW + x_hi]), HALF2, HALF2);
        u64 dE2 = fma2(pk2(D[row + x_lo + 1],  D[row + x_hi + 1]),  HALF2, HALF2);
        u64 dW2 = fma2(pk2(D[row + x_lo - 1],  D[row + x_hi - 1]),  HALF2, HALF2);

        // image / albedo loads for this row
        const float g0l = I0[row + x_lo], g0h = I0[row + x_hi];
        const float g1l = I1[row + x_lo], g1h = I1[row + x_hi];
        const float g2l = I2[row + x_lo], g2h = I2[row + x_hi];
        const float all_ = A2[row + x_lo], alh = A2[row + x_hi];

        const float vf  = (y     - 256.0f) * INVF;
        const float vNf = (y - 1 - 256.0f) * INVF;
        const float vSf = (y + 1 - 256.0f) * INVF;
        const u64 v2  = bcast2(vf);
        const u64 vN2 = bcast2(vNf);
        const u64 vS2 = bcast2(vSf);

        // depth differences
        const u64 dCE = sub2(dC2, dE2);   // dc - dE  (= awz)
        const u64 dSC = sub2(dS2, dC2);   // dS - dc  (= asz)
        const u64 dCW = sub2(dC2, dW2);   // dc - dW  (= aez)
        const u64 dNC = sub2(dN2, dC2);   // dN - dc  (= anz)

        const u64 vdc = mul2(v2, dC2);
        const u64 awx = fms2(u2, dC2, mul2(uE2, dE2));
        const u64 awy = mul2(v2, dCE);
        const u64 asx = mul2(u2, dSC);
        const u64 asy = fms2(vS2, dS2, vdc);
        const u64 aex = fms2(u2, dC2, mul2(uW2, dW2));
        const u64 aey = mul2(v2, dCW);
        const u64 anx = mul2(u2, dNC);
        const u64 any2 = fms2(vN2, dN2, vdc);

        // normal = cross(vw,vs) + cross(ve,vn)
        const u64 nx = add2(fms2(awy, dSC, mul2(dCE, asy)),
                            fms2(aey, dNC, mul2(dCW, any2)));
        const u64 ny = add2(fms2(dCE, asx, mul2(awx, dSC)),
                            fms2(dCW, anx, mul2(aex, dNC)));
        const u64 nz = add2(fms2(awx, asy, mul2(awy, asx)),
                            fms2(aex, any2, mul2(aey, anx)));

        const u64 xx = mul2(nx, nx);
        const u64 yy = mul2(ny, ny);
        const u64 zz = mul2(nz, nz);
        const u64 mag2v = add2(xx, add2(yy, zz));

        float m2l, m2h;
        upk2(mag2v, m2l, m2h);
        const u64 r2inv = pk2(rsqrtf(m2l), rsqrtf(m2h));  // 1/mag
        const u64 mag = mul2(mag2v, r2inv);               // mag

        u64 Nv[9];
        Nv[0] = mul2(C0_2, mag);
        Nv[1] = mul2(C1_2, nz);
        Nv[2] = mul2(C1_2, nx);
        Nv[3] = mul2(C1_2, ny);
        const u64 c2i = mul2(C2_2, r2inv);
        const u64 c3i = mul2(C3_2, r2inv);
        const u64 c4i = mul2(C4_2, r2inv);
        Nv[4] = mul2(c2i, fms2(THREE2, zz, mag2v));   // (2z2-x2-y2) = 3z2 - mag2
        Nv[5] = mul2(c3i, mul2(nx, nz));
        Nv[6] = mul2(c3i, mul2(ny, nz));
        Nv[7] = mul2(c4i, sub2(xx, yy));
        Nv[8] = mul2(c3i, mul2(nx, ny));

        // mask / rho / rhs   (b*mask*rho == b*rho since rho carries mask)
        const float m0l = fmaf(g0l, 0.5f, 0.5f);
        const float m0h = fmaf(g0h, 0.5f, 0.5f);
        const float kl = (m0l != 0.0f) ? 1.0f : 0.0f;
        const float kh = (v_hi && (m0h != 0.0f)) ? 1.0f : 0.0f;
        const u64 rho2 = pk2(all_ * kl, alh * kh);
        const u64 w2 = mul2(rho2, rho2);
        const u64 r0v = mul2(pk2(m0l, m0h), rho2);
        const u64 r1v = mul2(pk2(fmaf(g1l, 0.5f, 0.5f), fmaf(g1h, 0.5f, 0.5f)), rho2);
        const u64 r2v = mul2(pk2(fmaf(g2l, 0.5f, 0.5f), fmaf(g2h, 0.5f, 0.5f)), rho2);

        u64 wN[9];
#pragma unroll
        for (int i = 0; i < 9; i++) wN[i] = mul2(w2, Nv[i]);

        {
            int k = 0;
#pragma unroll
            for (int i = 0; i < 9; i++)
#pragma unroll
                for (int j = i; j < 9; j++) { s2[k] = fma2(wN[i], Nv[j], s2[k]); k++; }
        }
#pragma unroll
        for (int i = 0; i < 9; i++) {
            s2[45 + i] = fma2(r0v, Nv[i], s2[45 + i]);
            s2[54 + i] = fma2(r1v, Nv[i], s2[54 + i]);
            s2[63 + i] = fma2(r2v, Nv[i], s2[63 + i]);
        }

        // roll center column
        dN2 = dC2;
        dC2 = dS2;
    }

    // block reduction: pair-sum -> warp shuffle -> smem -> per-block partial (no atomics)
    __shared__ float red[4][NACC];
    const int lane = tid & 31;
    const int warp = tid >> 5;
#pragma unroll
    for (int k = 0; k < NACC; k++) {
        float lo, hi;
        upk2(s2[k], lo, hi);
        float v = lo + hi;
#pragma unroll
        for (int off = 16; off > 0; off >>= 1)
            v += __shfl_down_sync(0xffffffffu, v, off);
        if (lane == 0) red[warp][k] = v;
    }
    __syncthreads();
    const size_t pidx = ((size_t)b * NPART + (size_t)xb * NSTR + st) * NACC;
    for (int k = tid; k < NACC; k += 128) {
        g_part[pidx + k] = red[0][k] + red[1][k] + red[2][k] + red[3][k];
    }
}

__global__ void solve_k(float* __restrict__ out) {
    const int b = blockIdx.x;
    __shared__ double acc[NACC];

    for (int k = threadIdx.x; k < NACC; k += blockDim.x) {
        double t = 0.0;
        const float* p = g_part + (size_t)b * NPART * NACC + k;
        for (int q = 0; q < NPART; q++) t += (double)p[q * NACC];
        acc[k] = t;
    }
    __syncthreads();

    if (threadIdx.x == 0) {
        double Aug[9][12];
        int k = 0;
        for (int i = 0; i < 9; i++)
            for (int j = i; j < 9; j++) {
                double a = acc[k]; k++;
                Aug[i][j] = a;
                Aug[j][i] = a;
            }
        for (int c = 0; c < 3; c++)
            for (int i = 0; i < 9; i++)
                Aug[i][9 + c] = acc[45 + 9 * c + i];

        // Gaussian elimination with partial pivoting
        for (int col = 0; col < 9; col++) {
            int piv = col;
            double best = fabs(Aug[col][col]);
            for (int r = col + 1; r < 9; r++) {
                double a = fabs(Aug[r][col]);
                if (a > best) { best = a; piv = r; }
            }
            if (piv != col) {
                for (int j = 0; j < 12; j++) {
                    double t = Aug[col][j]; Aug[col][j] = Aug[piv][j]; Aug[piv][j] = t;
                }
            }
            double invp = 1.0 / Aug[col][col];
            for (int r = col + 1; r < 9; r++) {
                double f = Aug[r][col] * invp;
                for (int j = col; j < 12; j++) Aug[r][j] -= f * Aug[col][j];
            }
        }

        double X[9][3];
        for (int i = 8; i >= 0; i--) {
            double di = 1.0 / Aug[i][i];
            for (int c = 0; c < 3; c++) {
                double t = Aug[i][9 + c];
                for (int j = i + 1; j < 9; j++) t -= Aug[i][j] * X[j][c];
                X[i][c] = t * di;
            }
        }

        for (int c = 0; c < 3; c++)
            for (int i = 0; i < 9; i++)
                out[b * 27 + c * 9 + i] = (float)X[i][c];
    }
}

extern "C" void kernel_launch(void* const* d_in, const int* in_sizes, int n_in,
                              void* d_out, int out_size) {
    const float* img = (const float*)d_in[0];   // input_img (B,3,H,W)
    const float* dep = (const float*)d_in[1];   // depth_target (B,1,H,W)
    const float* alb = (const float*)d_in[2];   // albedo (B,3,H,W)
    int B = in_sizes[1] / (HH * WW);
    if (B > BMAX) B = BMAX;

    dim3 grid(NXB, NSTR, B);
    accum_k<<<grid, 128>>>(img, dep, alb);
    solve_k<<<B, 96>>>((float*)d_out);
}

// round 4
// speedup vs baseline: 1.4868x; 1.4868x over previous
#include <cuda_runtime.h>
#include <math.h>

#define HH 512
#define WW 512
#define NACC 72          // 45 AtA upper-tri + 27 Atb
#define NXB 2
#define NSTR 37
#define NPART (NXB * NSTR)   // 74 blocks per batch image
#define BMAX 8

__device__ float g_part[BMAX * NPART * NACC];

typedef unsigned long long u64;

__device__ __forceinline__ u64 pk2(float lo, float hi) {
    u64 r; asm("mov.b64 %0,{%1,%2};" : "=l"(r) : "f"(lo), "f"(hi)); return r;
}
__device__ __forceinline__ void upk2(u64 a, float& lo, float& hi) {
    asm("mov.b64 {%0,%1},%2;" : "=f"(lo), "=f"(hi) : "l"(a));
}
__device__ __forceinline__ u64 fma2(u64 a, u64 b, u64 c) {
    u64 d; asm("fma.rn.f32x2 %0,%1,%2,%3;" : "=l"(d) : "l"(a), "l"(b), "l"(c)); return d;
}
__device__ __forceinline__ u64 mul2(u64 a, u64 b) {
    u64 d; asm("mul.rn.f32x2 %0,%1,%2;" : "=l"(d) : "l"(a), "l"(b)); return d;
}
__device__ __forceinline__ u64 add2(u64 a, u64 b) {
    u64 d; asm("add.rn.f32x2 %0,%1,%2;" : "=l"(d) : "l"(a), "l"(b)); return d;
}
__device__ __forceinline__ u64 neg2(u64 a) { return a ^ 0x8000000080000000ULL; }
// a - b  (fma(b, -1, a): single rounding of exact difference)
__device__ __forceinline__ u64 sub2(u64 a, u64 b) { return fma2(b, 0xBF800000BF800000ULL, a); }
// a*b - c
__device__ __forceinline__ u64 fms2(u64 a, u64 b, u64 c) { return fma2(a, b, neg2(c)); }
__device__ __forceinline__ u64 bcast2(float v) { return pk2(v, v); }

__global__ __launch_bounds__(128) void accum_k(const float* __restrict__ img,
                                               const float* __restrict__ dep,
                                               const float* __restrict__ alb) {
    const int tid = threadIdx.x;
    const int xb = blockIdx.x;   // 0..1
    const int st = blockIdx.y;   // 0..36
    const int b  = blockIdx.z;

    const int x_lo = 1 + xb * 256 + tid;    // <= 384, always valid
    int x_hi = x_lo + 128;
    const bool v_hi = (x_hi <= 510);
    if (!v_hi) x_hi = 510;                  // clamp; contribution zeroed below

    const int y0 = 1 + (510 * st) / NSTR;
    const int y1 = 1 + (510 * (st + 1)) / NSTR;

    const float* __restrict__ D  = dep + (size_t)b * HH * WW;
    const float* __restrict__ I0 = img + (size_t)b * 3 * HH * WW;
    const float* __restrict__ I1 = I0 + HH * WW;
    const float* __restrict__ I2 = I1 + HH * WW;
    const float* __restrict__ A2 = alb + (size_t)b * 3 * HH * WW + 2 * HH * WW;

    const float INVF = (float)(1.0 / 608.365);
    const double PI_ = 3.14159;
    const float C0 = (float)(PI_ * sqrt(1.0 / (4.0 * PI_)));
    const float C1 = (float)(2.0 * PI_ / 3.0 * sqrt(3.0 / (4.0 * PI_)));
    const float C2 = (float)(PI_ / 4.0 * 0.5 * sqrt(5.0 / (4.0 * PI_)));
    const float C3 = (float)(PI_ / 4.0 * 3.0 * sqrt(5.0 / (12.0 * PI_)));
    const float C4 = (float)(PI_ / 4.0 * 3.0 * sqrt(5.0 / (48.0 * PI_)));
    const u64 C0_2 = bcast2(C0), C1_2 = bcast2(C1), C2_2 = bcast2(C2);
    const u64 C3_2 = bcast2(C3), C4_2 = bcast2(C4);
    const u64 HALF2  = 0x3F0000003F000000ULL;
    const u64 THREE2 = 0x4040000040400000ULL;

    // per-thread-constant x coordinates (packed)
    const u64 u2  = pk2((x_lo     - 256.0f) * INVF, (x_hi     - 256.0f) * INVF);
    const u64 uE2 = pk2((x_lo + 1 - 256.0f) * INVF, (x_hi + 1 - 256.0f) * INVF);
    const u64 uW2 = pk2((x_lo - 1 - 256.0f) * INVF, (x_hi - 1 - 256.0f) * INVF);

    u64 s2[NACC];
#pragma unroll
    for (int k = 0; k < NACC; k++) s2[k] = 0ULL;

    // preload center-column depth, rows y0-1 and y0 (transform d -> (d+1)/2)
    u64 dN2 = fma2(pk2(D[(y0 - 1) * WW + x_lo], D[(y0 - 1) * WW + x_hi]), HALF2, HALF2);
    u64 dC2 = fma2(pk2(D[y0 * WW + x_lo],       D[y0 * WW + x_hi]),       HALF2, HALF2);

    for (int y = y0; y < y1; y++) {
        const int row = y * WW;
        // fresh loads: south center, east, west (3 depth loads/pixel)
        u64 dS2 = fma2(pk2(D[row + WW + x_lo], D[row + WW + x_hi]), HALF2, HALF2);
        u64 dE2 = fma2(pk2(D[row + x_lo + 1],  D[row + x_hi + 1]),  HALF2, HALF2);
        u64 dW2 = fma2(pk2(D[row + x_lo - 1],  D[row + x_hi - 1]),  HALF2, HALF2);

        // image / albedo loads for this row
        const float g0l = I0[row + x_lo], g0h = I0[row + x_hi];
        const float g1l = I1[row + x_lo], g1h = I1[row + x_hi];
        const float g2l = I2[row + x_lo], g2h = I2[row + x_hi];
        const float all_ = A2[row + x_lo], alh = A2[row + x_hi];

        const float vf  = (y     - 256.0f) * INVF;
        const float vNf = (y - 1 - 256.0f) * INVF;
        const float vSf = (y + 1 - 256.0f) * INVF;
        const u64 v2  = bcast2(vf);
        const u64 vN2 = bcast2(vNf);
        const u64 vS2 = bcast2(vSf);

        // depth differences
        const u64 dCE = sub2(dC2, dE2);   // dc - dE  (= awz)
        const u64 dSC = sub2(dS2, dC2);   // dS - dc  (= asz)
        const u64 dCW = sub2(dC2, dW2);   // dc - dW  (= aez)
        const u64 dNC = sub2(dN2, dC2);   // dN - dc  (= anz)

        const u64 vdc = mul2(v2, dC2);
        const u64 awx = fms2(u2, dC2, mul2(uE2, dE2));
        const u64 awy = mul2(v2, dCE);
        const u64 asx = mul2(u2, dSC);
        const u64 asy = fms2(vS2, dS2, vdc);
        const u64 aex = fms2(u2, dC2, mul2(uW2, dW2));
        const u64 aey = mul2(v2, dCW);
        const u64 anx = mul2(u2, dNC);
        const u64 any2 = fms2(vN2, dN2, vdc);

        // normal = cross(vw,vs) + cross(ve,vn)
        const u64 nx = add2(fms2(awy, dSC, mul2(dCE, asy)),
                            fms2(aey, dNC, mul2(dCW, any2)));
        const u64 ny = add2(fms2(dCE, asx, mul2(awx, dSC)),
                            fms2(dCW, anx, mul2(aex, dNC)));
        const u64 nz = add2(fms2(awx, asy, mul2(awy, asx)),
                            fms2(aex, any2, mul2(aey, anx)));

        const u64 xx = mul2(nx, nx);
        const u64 yy = mul2(ny, ny);
        const u64 zz = mul2(nz, nz);
        const u64 mag2v = add2(xx, add2(yy, zz));

        float m2l, m2h;
        upk2(mag2v, m2l, m2h);
        const u64 r2inv = pk2(rsqrtf(m2l), rsqrtf(m2h));  // 1/mag
        const u64 mag = mul2(mag2v, r2inv);               // mag

        u64 Nv[9];
        Nv[0] = mul2(C0_2, mag);
        Nv[1] = mul2(C1_2, nz);
        Nv[2] = mul2(C1_2, nx);
        Nv[3] = mul2(C1_2, ny);
        const u64 c2i = mul2(C2_2, r2inv);
        const u64 c3i = mul2(C3_2, r2inv);
        const u64 c4i = mul2(C4_2, r2inv);
        Nv[4] = mul2(c2i, fms2(THREE2, zz, mag2v));   // (2z2-x2-y2) = 3z2 - mag2
        Nv[5] = mul2(c3i, mul2(nx, nz));
        Nv[6] = mul2(c3i, mul2(ny, nz));
        Nv[7] = mul2(c4i, sub2(xx, yy));
        Nv[8] = mul2(c3i, mul2(nx, ny));

        // mask / rho / rhs   (b*mask*rho == b*rho since rho carries mask)
        const float m0l = fmaf(g0l, 0.5f, 0.5f);
        const float m0h = fmaf(g0h, 0.5f, 0.5f);
        const float kl = (m0l != 0.0f) ? 1.0f : 0.0f;
        const float kh = (v_hi && (m0h != 0.0f)) ? 1.0f : 0.0f;
        const u64 rho2 = pk2(all_ * kl, alh * kh);
        const u64 w2 = mul2(rho2, rho2);
        const u64 r0v = mul2(pk2(m0l, m0h), rho2);
        const u64 r1v = mul2(pk2(fmaf(g1l, 0.5f, 0.5f), fmaf(g1h, 0.5f, 0.5f)), rho2);
        const u64 r2v = mul2(pk2(fmaf(g2l, 0.5f, 0.5f), fmaf(g2h, 0.5f, 0.5f)), rho2);

        u64 wN[9];
#pragma unroll
        for (int i = 0; i < 9; i++) wN[i] = mul2(w2, Nv[i]);

        {
            int k = 0;
#pragma unroll
            for (int i = 0; i < 9; i++)
#pragma unroll
                for (int j = i; j < 9; j++) { s2[k] = fma2(wN[i], Nv[j], s2[k]); k++; }
        }
#pragma unroll
        for (int i = 0; i < 9; i++) {
            s2[45 + i] = fma2(r0v, Nv[i], s2[45 + i]);
            s2[54 + i] = fma2(r1v, Nv[i], s2[54 + i]);
            s2[63 + i] = fma2(r2v, Nv[i], s2[63 + i]);
        }

        // roll center column
        dN2 = dC2;
        dC2 = dS2;
    }

    // block reduction: pair-sum -> warp shuffle -> smem -> per-block partial (no atomics)
    __shared__ float red[4][NACC];
    const int lane = tid & 31;
    const int warp = tid >> 5;
#pragma unroll
    for (int k = 0; k < NACC; k++) {
        float lo, hi;
        upk2(s2[k], lo, hi);
        float v = lo + hi;
#pragma unroll
        for (int off = 16; off > 0; off >>= 1)
            v += __shfl_down_sync(0xffffffffu, v, off);
        if (lane == 0) red[warp][k] = v;
    }
    __syncthreads();
    const size_t pidx = ((size_t)b * NPART + (size_t)xb * NSTR + st) * NACC;
    for (int k = tid; k < NACC; k += 128) {
        g_part[pidx + k] = red[0][k] + red[1][k] + red[2][k] + red[3][k];
    }
}

// upper-tri index for i<=j: row-i start = 9i - i(i-1)/2
__device__ __forceinline__ int triidx(int i, int j) {
    return 9 * i - (i * (i - 1)) / 2 + (j - i);
}

__global__ __launch_bounds__(128) void solve_k(float* __restrict__ out) {
    const int b = blockIdx.x;
    __shared__ double acc[NACC];

    // Phase 1: reduce the 74 per-block partials (72 threads, one per element)
    if (threadIdx.x < NACC) {
        const float* p = g_part + (size_t)b * NPART * NACC + threadIdx.x;
        double t = 0.0;
#pragma unroll 2
        for (int q = 0; q < NPART; q++) t += (double)p[q * NACC];
        acc[threadIdx.x] = t;
    }
    __syncthreads();

    // Phase 2: 9-lane parallel Gauss-Jordan (SPD, no pivoting), rows in registers
    const int lane = threadIdx.x;
    if (lane < 9) {
        const unsigned MASK = 0x1FFu;
        double row[12];
#pragma unroll
        for (int j = 0; j < 9; j++) {
            int i = lane < j ? lane : j;
            int jj = lane < j ? j : lane;
            row[j] = acc[triidx(i, jj)];
        }
#pragma unroll
        for (int c = 0; c < 3; c++) row[9 + c] = acc[45 + 9 * c + lane];

#pragma unroll
        for (int col = 0; col < 9; col++) {
            const double pc = __shfl_sync(MASK, row[col], col);
            const double invp = 1.0 / pc;
            double piv[12];
#pragma unroll
            for (int j = 0; j < 12; j++)
                piv[j] = __shfl_sync(MASK, row[j], col) * invp;
            if (lane != col) {
                const double f = row[col];
#pragma unroll
                for (int j = 0; j < 12; j++) row[j] -= f * piv[j];
            } else {
#pragma unroll
                for (int j = 0; j < 12; j++) row[j] = piv[j];
            }
        }

        // diagonal is 1 now; rhs columns hold the solution
#pragma unroll
        for (int c = 0; c < 3; c++)
            out[b * 27 + c * 9 + lane] = (float)row[9 + c];
    }
}

extern "C" void kernel_launch(void* const* d_in, const int* in_sizes, int n_in,
                              void* d_out, int out_size) {
    const float* img = (const float*)d_in[0];   // input_img (B,3,H,W)
    const float* dep = (const float*)d_in[1];   // depth_target (B,1,H,W)
    const float* alb = (const float*)d_in[2];   // albedo (B,3,H,W)
    int B = in_sizes[1] / (HH * WW);
    if (B > BMAX) B = BMAX;

    dim3 grid(NXB, NSTR, B);
    accum_k<<<grid, 128>>>(img, dep, alb);
    solve_k<<<B, 128>>>((float*)d_out);
}

// round 5
// speedup vs baseline: 1.9669x; 1.3230x over previous
#include <cuda_runtime.h>
#include <math.h>

#define HH 512
#define WW 512
#define NACC 72          // 45 AtA upper-tri + 27 Atb
#define NXB 2
#define NSTR 37
#define NPART (NXB * NSTR)   // 74 blocks per batch image
#define BMAX 8

__device__ float g_part[BMAX * NPART * NACC];

typedef unsigned long long u64;

__device__ __forceinline__ u64 pk2(float lo, float hi) {
    u64 r; asm("mov.b64 %0,{%1,%2};" : "=l"(r) : "f"(lo), "f"(hi)); return r;
}
__device__ __forceinline__ void upk2(u64 a, float& lo, float& hi) {
    asm("mov.b64 {%0,%1},%2;" : "=f"(lo), "=f"(hi) : "l"(a));
}
__device__ __forceinline__ u64 fma2(u64 a, u64 b, u64 c) {
    u64 d; asm("fma.rn.f32x2 %0,%1,%2,%3;" : "=l"(d) : "l"(a), "l"(b), "l"(c)); return d;
}
__device__ __forceinline__ u64 mul2(u64 a, u64 b) {
    u64 d; asm("mul.rn.f32x2 %0,%1,%2;" : "=l"(d) : "l"(a), "l"(b)); return d;
}
__device__ __forceinline__ u64 add2(u64 a, u64 b) {
    u64 d; asm("add.rn.f32x2 %0,%1,%2;" : "=l"(d) : "l"(a), "l"(b)); return d;
}
__device__ __forceinline__ u64 neg2(u64 a) { return a ^ 0x8000000080000000ULL; }
__device__ __forceinline__ u64 sub2(u64 a, u64 b) { return fma2(b, 0xBF800000BF800000ULL, a); }
__device__ __forceinline__ u64 fms2(u64 a, u64 b, u64 c) { return fma2(a, b, neg2(c)); }
__device__ __forceinline__ u64 bcast2(float v) { return pk2(v, v); }

__global__ __launch_bounds__(128) void accum_k(const float* __restrict__ img,
                                               const float* __restrict__ dep,
                                               const float* __restrict__ alb) {
    const int tid = threadIdx.x;
    const int xb = blockIdx.x;   // 0..1
    const int st = blockIdx.y;   // 0..36
    const int b  = blockIdx.z;

    const int x_lo = 1 + xb * 256 + tid;    // <= 384, always valid
    int x_hi = x_lo + 128;
    const bool v_hi = (x_hi <= 510);
    if (!v_hi) x_hi = 510;                  // clamp; contribution zeroed below

    const int y0 = 1 + (510 * st) / NSTR;
    const int y1 = 1 + (510 * (st + 1)) / NSTR;

    const float* __restrict__ D  = dep + (size_t)b * HH * WW;
    const float* __restrict__ I0 = img + (size_t)b * 3 * HH * WW;
    const float* __restrict__ I1 = I0 + HH * WW;
    const float* __restrict__ I2 = I1 + HH * WW;
    const float* __restrict__ A2 = alb + (size_t)b * 3 * HH * WW + 2 * HH * WW;

    const float INVF = (float)(1.0 / 608.365);
    const double PI_ = 3.14159;
    const float C0 = (float)(PI_ * sqrt(1.0 / (4.0 * PI_)));
    const float C1 = (float)(2.0 * PI_ / 3.0 * sqrt(3.0 / (4.0 * PI_)));
    const float C2 = (float)(PI_ / 4.0 * 0.5 * sqrt(5.0 / (4.0 * PI_)));
    const float C3 = (float)(PI_ / 4.0 * 3.0 * sqrt(5.0 / (12.0 * PI_)));
    const float C4 = (float)(PI_ / 4.0 * 3.0 * sqrt(5.0 / (48.0 * PI_)));
    const u64 C0_2 = bcast2(C0), C1_2 = bcast2(C1), C2_2 = bcast2(C2);
    const u64 C3_2 = bcast2(C3), C4_2 = bcast2(C4);
    const u64 HALF2  = 0x3F0000003F000000ULL;
    const u64 THREE2 = 0x4040000040400000ULL;

    const u64 u2  = pk2((x_lo     - 256.0f) * INVF, (x_hi     - 256.0f) * INVF);
    const u64 uE2 = pk2((x_lo + 1 - 256.0f) * INVF, (x_hi + 1 - 256.0f) * INVF);
    const u64 uW2 = pk2((x_lo - 1 - 256.0f) * INVF, (x_hi - 1 - 256.0f) * INVF);

    u64 s2[NACC];
#pragma unroll
    for (int k = 0; k < NACC; k++) s2[k] = 0ULL;

    u64 dN2 = fma2(pk2(D[(y0 - 1) * WW + x_lo], D[(y0 - 1) * WW + x_hi]), HALF2, HALF2);
    u64 dC2 = fma2(pk2(D[y0 * WW + x_lo],       D[y0 * WW + x_hi]),       HALF2, HALF2);

    for (int y = y0; y < y1; y++) {
        const int row = y * WW;
        u64 dS2 = fma2(pk2(D[row + WW + x_lo], D[row + WW + x_hi]), HALF2, HALF2);
        u64 dE2 = fma2(pk2(D[row + x_lo + 1],  D[row + x_hi + 1]),  HALF2, HALF2);
        u64 dW2 = fma2(pk2(D[row + x_lo - 1],  D[row + x_hi - 1]),  HALF2, HALF2);

        const float g0l = I0[row + x_lo], g0h = I0[row + x_hi];
        const float g1l = I1[row + x_lo], g1h = I1[row + x_hi];
        const float g2l = I2[row + x_lo], g2h = I2[row + x_hi];
        const float all_ = A2[row + x_lo], alh = A2[row + x_hi];

        const float vf  = (y     - 256.0f) * INVF;
        const float vNf = (y - 1 - 256.0f) * INVF;
        const float vSf = (y + 1 - 256.0f) * INVF;
        const u64 v2  = bcast2(vf);
        const u64 vN2 = bcast2(vNf);
        const u64 vS2 = bcast2(vSf);

        const u64 dCE = sub2(dC2, dE2);
        const u64 dSC = sub2(dS2, dC2);
        const u64 dCW = sub2(dC2, dW2);
        const u64 dNC = sub2(dN2, dC2);

        const u64 vdc = mul2(v2, dC2);
        const u64 awx = fms2(u2, dC2, mul2(uE2, dE2));
        const u64 awy = mul2(v2, dCE);
        const u64 asx = mul2(u2, dSC);
        const u64 asy = fms2(vS2, dS2, vdc);
        const u64 aex = fms2(u2, dC2, mul2(uW2, dW2));
        const u64 aey = mul2(v2, dCW);
        const u64 anx = mul2(u2, dNC);
        const u64 any2 = fms2(vN2, dN2, vdc);

        const u64 nx = add2(fms2(awy, dSC, mul2(dCE, asy)),
                            fms2(aey, dNC, mul2(dCW, any2)));
        const u64 ny = add2(fms2(dCE, asx, mul2(awx, dSC)),
                            fms2(dCW, anx, mul2(aex, dNC)));
        const u64 nz = add2(fms2(awx, asy, mul2(awy, asx)),
                            fms2(aex, any2, mul2(aey, anx)));

        const u64 xx = mul2(nx, nx);
        const u64 yy = mul2(ny, ny);
        const u64 zz = mul2(nz, nz);
        const u64 mag2v = add2(xx, add2(yy, zz));

        float m2l, m2h;
        upk2(mag2v, m2l, m2h);
        const u64 r2inv = pk2(rsqrtf(m2l), rsqrtf(m2h));  // 1/mag
        const u64 mag = mul2(mag2v, r2inv);               // mag

        u64 Nv[9];
        Nv[0] = mul2(C0_2, mag);
        Nv[1] = mul2(C1_2, nz);
        Nv[2] = mul2(C1_2, nx);
        Nv[3] = mul2(C1_2, ny);
        const u64 c2i = mul2(C2_2, r2inv);
        const u64 c3i = mul2(C3_2, r2inv);
        const u64 c4i = mul2(C4_2, r2inv);
        Nv[4] = mul2(c2i, fms2(THREE2, zz, mag2v));
        Nv[5] = mul2(c3i, mul2(nx, nz));
        Nv[6] = mul2(c3i, mul2(ny, nz));
        Nv[7] = mul2(c4i, sub2(xx, yy));
        Nv[8] = mul2(c3i, mul2(nx, ny));

        const float m0l = fmaf(g0l, 0.5f, 0.5f);
        const float m0h = fmaf(g0h, 0.5f, 0.5f);
        const float kl = (m0l != 0.0f) ? 1.0f : 0.0f;
        const float kh = (v_hi && (m0h != 0.0f)) ? 1.0f : 0.0f;
        const u64 rho2 = pk2(all_ * kl, alh * kh);
        const u64 w2 = mul2(rho2, rho2);
        const u64 r0v = mul2(pk2(m0l, m0h), rho2);
        const u64 r1v = mul2(pk2(fmaf(g1l, 0.5f, 0.5f), fmaf(g1h, 0.5f, 0.5f)), rho2);
        const u64 r2v = mul2(pk2(fmaf(g2l, 0.5f, 0.5f), fmaf(g2h, 0.5f, 0.5f)), rho2);

        u64 wN[9];
#pragma unroll
        for (int i = 0; i < 9; i++) wN[i] = mul2(w2, Nv[i]);

        {
            int k = 0;
#pragma unroll
            for (int i = 0; i < 9; i++)
#pragma unroll
                for (int j = i; j < 9; j++) { s2[k] = fma2(wN[i], Nv[j], s2[k]); k++; }
        }
#pragma unroll
        for (int i = 0; i < 9; i++) {
            s2[45 + i] = fma2(r0v, Nv[i], s2[45 + i]);
            s2[54 + i] = fma2(r1v, Nv[i], s2[54 + i]);
            s2[63 + i] = fma2(r2v, Nv[i], s2[63 + i]);
        }

        dN2 = dC2;
        dC2 = dS2;
    }

    __shared__ float red[4][NACC];
    const int lane = tid & 31;
    const int warp = tid >> 5;
#pragma unroll
    for (int k = 0; k < NACC; k++) {
        float lo, hi;
        upk2(s2[k], lo, hi);
        float v = lo + hi;
#pragma unroll
        for (int off = 16; off > 0; off >>= 1)
            v += __shfl_down_sync(0xffffffffu, v, off);
        if (lane == 0) red[warp][k] = v;
    }
    __syncthreads();
    const size_t pidx = ((size_t)b * NPART + (size_t)xb * NSTR + st) * NACC;
    for (int k = tid; k < NACC; k += 128) {
        g_part[pidx + k] = red[0][k] + red[1][k] + red[2][k] + red[3][k];
    }
}

// upper-tri index for i<=j
__device__ __forceinline__ int triidx(int i, int j) {
    return 9 * i - (i * (i - 1)) / 2 + (j - i);
}

// GJ row layout: [0..8]=A, [9..11]=b (3 rhs), [12..20]=identity -> A^{-1}
#define NCOL 21

__global__ __launch_bounds__(128) void solve_k(float* __restrict__ out) {
    const int b = blockIdx.x;
    __shared__ double acc[NACC];

    // Phase 1: reduce 74 partials per element; fully unrolled -> deep MLP
    if (threadIdx.x < NACC) {
        const float* p = g_part + (size_t)b * NPART * NACC + threadIdx.x;
        float f[NPART];
#pragma unroll
        for (int q = 0; q < NPART; q++) f[q] = p[q * NACC];
        double t = 0.0;
#pragma unroll
        for (int q = 0; q < NPART; q++) t += (double)f[q];
        acc[threadIdx.x] = t;
    }
    __syncthreads();

    if (threadIdx.x >= 32) return;
    const int lane = threadIdx.x;
    const unsigned FULL = 0xFFFFFFFFu;

    // Load fp64 row of A and b (valid lanes 0..8; others zero)
    double A64[9], b64[3];
#pragma unroll
    for (int j = 0; j < 9; j++) {
        int i = lane < j ? lane : j;
        int jj = lane < j ? j : lane;
        int idx = triidx(i, jj);
        A64[j] = (lane < 9) ? acc[idx] : 0.0;
    }
#pragma unroll
    for (int c = 0; c < 3; c++)
        b64[c] = (lane < 9) ? acc[45 + 9 * c + lane] : 0.0;

    // Phase 2a: fp32 Gauss-Jordan on [A | b | I]  (SPD -> no pivoting)
    float row[NCOL];
#pragma unroll
    for (int j = 0; j < 9; j++) row[j] = (float)A64[j];
#pragma unroll
    for (int c = 0; c < 3; c++) row[9 + c] = (float)b64[c];
#pragma unroll
    for (int j = 0; j < 9; j++) row[12 + j] = (lane == j) ? 1.0f : 0.0f;

#pragma unroll
    for (int col = 0; col < 9; col++) {
        const float pc = __shfl_sync(FULL, row[col], col);
        const float invp = __frcp_rn(pc);
        float piv[NCOL];
#pragma unroll
        for (int j = 0; j < NCOL; j++)
            piv[j] = __shfl_sync(FULL, row[j], col) * invp;
        if (lane == col) {
#pragma unroll
            for (int j = 0; j < NCOL; j++) row[j] = piv[j];
        } else {
            const float f = row[col];
#pragma unroll
            for (int j = 0; j < NCOL; j++) row[j] = fmaf(-f, piv[j], row[j]);
        }
    }
    // row[9..11] = x0 (fp32), row[12..20] = A^{-1} row (fp32)

    // Phase 2b: one refinement step. r = b - A*x0 in fp64; dx = Minv*r in fp32.
#pragma unroll
    for (int c = 0; c < 3; c++) {
        // broadcast x0[j] (fp32) from lane j, accumulate residual in fp64
        double r = b64[c];
#pragma unroll
        for (int j = 0; j < 9; j++) {
            float x0j = __shfl_sync(FULL, row[9 + c], j);
            r -= A64[j] * (double)x0j;
        }
        float rf = (float)r;
        float dx = 0.0f;
#pragma unroll
        for (int j = 0; j < 9; j++) {
            float rj = __shfl_sync(FULL, rf, j);
            dx = fmaf(row[12 + j], rj, dx);
        }
        if (lane < 9)
            out[b * 27 + c * 9 + lane] = (float)((double)row[9 + c] + (double)dx);
    }
}

extern "C" void kernel_launch(void* const* d_in, const int* in_sizes, int n_in,
                              void* d_out, int out_size) {
    const float* img = (const float*)d_in[0];   // input_img (B,3,H,W)
    const float* dep = (const float*)d_in[1];   // depth_target (B,1,H,W)
    const float* alb = (const float*)d_in[2];   // albedo (B,3,H,W)
    int B = in_sizes[1] / (HH * WW);
    if (B > BMAX) B = BMAX;

    dim3 grid(NXB, NSTR, B);
    accum_k<<<grid, 128>>>(img, dep, alb);
    solve_k<<<B, 128>>>((float*)d_out);
}